// round 14
// baseline (speedup 1.0000x reference)
#include <cuda_runtime.h>
#include <math.h>

// ---------------- problem constants ----------------
#define MTOT  131072          // B*T*H*W rows, m = ((b*T+t)*H+h)*W+w
#define QLD   772             // qkv smem row stride (floats): mult of 4, !=0 mod 32
#define XLD   260             // xc smem row stride

// ---------------- scratch (device globals; no allocs) ----------------
__device__ float g_up[(size_t)MTOT * 512];   // up-projection output [M,512] (x_m | z)
__device__ float g_hs[(size_t)MTOT * 256];   // h_state [M,256]

__device__ __forceinline__ float siluf(float x) { return x / (1.f + __expf(-x)); }

// ---------------- packed f32x2 helpers (B300 double-rate fp32) ----------------
__device__ __forceinline__ unsigned long long pack2(float lo, float hi) {
    unsigned long long r;
    asm("mov.b64 %0, {%1, %2};" : "=l"(r) : "f"(lo), "f"(hi));
    return r;
}
__device__ __forceinline__ void fma2(unsigned long long& d,
                                     unsigned long long a, unsigned long long b) {
    asm("fma.rn.f32x2 %0, %1, %2, %0;" : "+l"(d) : "l"(a), "l"(b));
}
__device__ __forceinline__ void unpack2(unsigned long long v, float& lo, float& hi) {
    asm("mov.b64 {%0, %1}, %2;" : "=f"(lo), "=f"(hi) : "l"(v));
}

// =====================================================================
// Kernel 1: up projection GEMM  up[m,n] = sum_k xs[m,k] * W_up[k,n]
//   128x128 tile, 8x8 micro (f32x2 packed), kc=64
// =====================================================================
__global__ __launch_bounds__(256) void k_up(const float* __restrict__ x,
                                            const float* __restrict__ Wup)
{
    extern __shared__ float sm[];
    float* As = sm;             // [64 k][128 m]
    float* Bs = sm + 64 * 128;  // [64 k][128 n]

    const int tid = threadIdx.x;
    const int n0 = blockIdx.x * 128;
    const int m0 = blockIdx.y * 128;
    const int hw0 = m0 & 1023;
    const int bt  = m0 >> 10;           // b*16 + t
    const float* xb = x + (size_t)(bt >> 4) * 2097152 + (size_t)(bt & 15) * 1024 + hw0;

    const int mx = tid & 15, ny = tid >> 4;
    const int l4 = (tid & 31) * 4, kr = tid >> 5;  // loader coords

    unsigned long long acc2[4][8];      // [m-pair][n]
#pragma unroll
    for (int i = 0; i < 4; i++)
#pragma unroll
        for (int j = 0; j < 8; j++) acc2[i][j] = 0ULL;

    for (int kc = 0; kc < 128; kc += 64) {
#pragma unroll
        for (int p = 0; p < 8; p++) {
            int k = kr + p * 8;
            *(float4*)(As + k * 128 + l4) = *(const float4*)(xb + (size_t)(kc + k) * 16384 + l4);
            *(float4*)(Bs + k * 128 + l4) = *(const float4*)(Wup + (size_t)(kc + k) * 512 + n0 + l4);
        }
        __syncthreads();
#pragma unroll 4
        for (int k = 0; k < 64; k++) {
            float4 a0 = *(const float4*)(As + k * 128 + mx * 4);
            float4 a1 = *(const float4*)(As + k * 128 + 64 + mx * 4);
            float4 b0 = *(const float4*)(Bs + k * 128 + ny * 4);
            float4 b1 = *(const float4*)(Bs + k * 128 + 64 + ny * 4);
            unsigned long long ap[4];
            ap[0] = pack2(a0.x, a0.y); ap[1] = pack2(a0.z, a0.w);
            ap[2] = pack2(a1.x, a1.y); ap[3] = pack2(a1.z, a1.w);
            unsigned long long bb[8];
            bb[0] = pack2(b0.x, b0.x); bb[1] = pack2(b0.y, b0.y);
            bb[2] = pack2(b0.z, b0.z); bb[3] = pack2(b0.w, b0.w);
            bb[4] = pack2(b1.x, b1.x); bb[5] = pack2(b1.y, b1.y);
            bb[6] = pack2(b1.z, b1.z); bb[7] = pack2(b1.w, b1.w);
#pragma unroll
            for (int i = 0; i < 4; i++)
#pragma unroll
                for (int j = 0; j < 8; j++) fma2(acc2[i][j], ap[i], bb[j]);
        }
        __syncthreads();
    }

    float acc[8][8];
#pragma unroll
    for (int i = 0; i < 4; i++)
#pragma unroll
        for (int j = 0; j < 8; j++) unpack2(acc2[i][j], acc[2 * i][j], acc[2 * i + 1][j]);

#pragma unroll
    for (int i = 0; i < 8; i++) {
        int m = m0 + mx * 4 + (i & 3) + ((i >> 2) << 6);
        float* ob = g_up + (size_t)m * 512 + n0;
        *(float4*)(ob + ny * 4)      = make_float4(acc[i][0], acc[i][1], acc[i][2], acc[i][3]);
        *(float4*)(ob + 64 + ny * 4) = make_float4(acc[i][4], acc[i][5], acc[i][6], acc[i][7]);
    }
}

// =====================================================================
// Kernel 2: fused conv/qkv/gates/mLSTM/LN/gating, one CTA per sequence
//   xc in smem; q/k/v via 16B broadcast loads (no shuffles, low regs)
// =====================================================================
struct SM2 {
    float qkv[16 * QLD];        // per t: q[0,256) k[256,512) v[512,768)
    float xcs[16 * XLD];        // conv+silu output rows
    float chat[4 * 16 * 16];
    float lf[4 * 17];
    float igv[64];
    float fgv[64];
    float red[2 * 8 * 16];      // [sum|sq][warp][t]
};

__global__ __launch_bounds__(256, 3) void k_mid(
    const float* __restrict__ cw,  const float* __restrict__ cb,
    const float* __restrict__ Wq,  const float* __restrict__ Wk,
    const float* __restrict__ Wv,
    const float* __restrict__ igw, const float* __restrict__ igb,
    const float* __restrict__ fgw, const float* __restrict__ fgb,
    const float* __restrict__ lnw, const float* __restrict__ skip)
{
    extern __shared__ char smraw[];
    SM2& s = *reinterpret_cast<SM2*>(smraw);
    const int tid  = threadIdx.x;
    const int lane = tid & 31;
    const int warp = tid >> 5;
    const int bl4  = tid & ~3;          // 4-channel block base
    const int e    = tid & 3;
    const int seq = blockIdx.x;
    const int b = seq >> 10, hw = seq & 1023;
    const size_t rowbase = ((size_t)(b * 16) << 10) + hw;   // + (t<<10) per step

    // ---- loop1: xm block via LDG.128 broadcast; conv window in 3 regs;
    //      xc -> smem; v = blockdiag(Wv)@xm -> qkv ----
    {
        float c0 = cw[tid], c1 = cw[256 + tid], c2 = cw[512 + tid], c3 = cw[768 + tid];
        float cbv = cb[tid];
        float4 wv = *(const float4*)(Wv + 4 * tid);
        float w0 = 0.f, w1 = 0.f, w2 = 0.f;   // xm[t-3], xm[t-2], xm[t-1] (own channel)
#pragma unroll
        for (int t = 0; t < 16; t++) {
            float4 xmb = *(const float4*)(g_up + (rowbase + ((size_t)t << 10)) * 512 + bl4);
            float xmt = (e == 0) ? xmb.x : (e == 1) ? xmb.y : (e == 2) ? xmb.z : xmb.w;
            float a = cbv + c3 * xmt;
            if (t >= 1) a += c2 * w2;
            if (t >= 2) a += c1 * w1;
            if (t >= 3) a += c0 * w0;
            s.xcs[t * XLD + tid] = siluf(a);
            s.qkv[t * QLD + 512 + tid] =
                wv.x * xmb.x + wv.y * xmb.y + wv.z * xmb.z + wv.w * xmb.w;
            w0 = w1; w1 = w2; w2 = xmt;
        }
    }
    __syncwarp();   // xc producers/consumers are within the same warp (4-lane blocks)

    // ---- loop2: q/k from xc block via LDS.128 broadcast ----
    {
        float4 wq = *(const float4*)(Wq + 4 * tid);
        float4 wk = *(const float4*)(Wk + 4 * tid);
#pragma unroll
        for (int t = 0; t < 16; t++) {
            float4 xcb = *(const float4*)(&s.xcs[t * XLD + bl4]);
            s.qkv[t * QLD + tid] =
                wq.x * xcb.x + wq.y * xcb.y + wq.z * xcb.z + wq.w * xcb.w;
            s.qkv[t * QLD + 256 + tid] =
                wk.x * xcb.x + wk.y * xcb.y + wk.z * xcb.z + wk.w * xcb.w;
        }
    }
    __syncthreads();

    // ---- gates: ig/fg [t,h] over 768 inputs; 16 lanes split-K + shfl reduce ----
    {
        int t = tid >> 4, p = tid & 15;
        const float* row = s.qkv + t * QLD;
        float ai[4] = {0.f, 0.f, 0.f, 0.f}, af[4] = {0.f, 0.f, 0.f, 0.f};
#pragma unroll
        for (int ii = 0; ii < 12; ii++) {
            int idx = p * 4 + ii * 64;
            float4 xv = *(const float4*)(row + idx);
            float vals[4] = {xv.x, xv.y, xv.z, xv.w};
#pragma unroll
            for (int ee = 0; ee < 4; ee++) {
                float val = vals[ee];
                float4 wi = *(const float4*)(igw + (idx + ee) * 4);
                float4 wf = *(const float4*)(fgw + (idx + ee) * 4);
                ai[0] += val * wi.x; ai[1] += val * wi.y; ai[2] += val * wi.z; ai[3] += val * wi.w;
                af[0] += val * wf.x; af[1] += val * wf.y; af[2] += val * wf.z; af[3] += val * wf.w;
            }
        }
#pragma unroll
        for (int off = 1; off < 16; off <<= 1) {
#pragma unroll
            for (int h = 0; h < 4; h++) {
                ai[h] += __shfl_xor_sync(0xffffffffu, ai[h], off);
                af[h] += __shfl_xor_sync(0xffffffffu, af[h], off);
            }
        }
        if (p == 0) {
#pragma unroll
            for (int h = 0; h < 4; h++) {
                s.igv[t * 4 + h] = ai[h] + igb[h];
                s.fgv[t * 4 + h] = af[h] + fgb[h];
            }
        }
    }
    __syncthreads();

    // ---- log-sigmoid of forget gates: parallel over 64 (t,h), then prefix ----
    if (tid < 64) {
        int t = tid >> 2, h = tid & 3;
        float xg = s.fgv[t * 4 + h];
        s.lf[h * 17 + t + 1] = fminf(xg, 0.f) - __logf(1.f + __expf(-fabsf(xg)));
    }
    __syncthreads();
    if (tid < 4) {
        int h = tid;
        float run = 0.f;
        s.lf[h * 17 + 0] = 0.f;
#pragma unroll
        for (int t = 0; t < 16; t++) {
            run += s.lf[h * 17 + t + 1];
            s.lf[h * 17 + t + 1] = run;
        }
    }
    __syncthreads();

    // ---- qk + gate matrix + normalizer -> chat (per head: 64 thr, 2x2 tiles) ----
    {
        int head = tid >> 6, w = tid & 63;
        int s0 = (w >> 3) * 2;
        int t0 = (w & 7) * 2;
        const float* q0 = s.qkv + s0 * QLD + head * 64;
        const float* q1 = q0 + QLD;
        const float* k0 = s.qkv + t0 * QLD + 256 + head * 64;
        const float* k1 = k0 + QLD;
        float qk00 = 0.f, qk01 = 0.f, qk10 = 0.f, qk11 = 0.f;
#pragma unroll 4
        for (int d4 = 0; d4 < 16; d4++) {
            float4 a0 = *(const float4*)(q0 + d4 * 4);
            float4 a1 = *(const float4*)(q1 + d4 * 4);
            float4 b0 = *(const float4*)(k0 + d4 * 4);
            float4 b1 = *(const float4*)(k1 + d4 * 4);
            qk00 += a0.x * b0.x + a0.y * b0.y + a0.z * b0.z + a0.w * b0.w;
            qk01 += a0.x * b1.x + a0.y * b1.y + a0.z * b1.z + a0.w * b1.w;
            qk10 += a1.x * b0.x + a1.y * b0.y + a1.z * b0.z + a1.w * b0.w;
            qk11 += a1.x * b1.x + a1.y * b1.y + a1.z * b1.z + a1.w * b1.w;
        }
        float qk[2][2] = {{qk00, qk01}, {qk10, qk11}};
        float logD[2][2], mymax[2];
#pragma unroll
        for (int si = 0; si < 2; si++) {
            int ss = s0 + si;
            mymax[si] = -INFINITY;
#pragma unroll
            for (int tj = 0; tj < 2; tj++) {
                int t_ = t0 + tj;
                float v = (t_ <= ss)
                    ? (s.lf[head * 17 + ss + 1] - s.lf[head * 17 + t_ + 1] + s.igv[t_ * 4 + head])
                    : -INFINITY;
                logD[si][tj] = v;
                mymax[si] = fmaxf(mymax[si], v);
            }
        }
#pragma unroll
        for (int off = 1; off < 8; off <<= 1) {
            mymax[0] = fmaxf(mymax[0], __shfl_xor_sync(0xffffffffu, mymax[0], off));
            mymax[1] = fmaxf(mymax[1], __shfl_xor_sync(0xffffffffu, mymax[1], off));
        }
        float Cc[2][2], rowsum[2] = {0.f, 0.f};
#pragma unroll
        for (int si = 0; si < 2; si++)
#pragma unroll
            for (int tj = 0; tj < 2; tj++) {
                float Dv = __expf(logD[si][tj] - mymax[si]);   // __expf(-inf)=0 masked
                float Cv = qk[si][tj] * 0.125f * Dv;
                Cc[si][tj] = Cv;
                rowsum[si] += Cv;
            }
#pragma unroll
        for (int off = 1; off < 8; off <<= 1) {
            rowsum[0] += __shfl_xor_sync(0xffffffffu, rowsum[0], off);
            rowsum[1] += __shfl_xor_sync(0xffffffffu, rowsum[1], off);
        }
#pragma unroll
        for (int si = 0; si < 2; si++) {
            float norm = fmaxf(fabsf(rowsum[si]), __expf(-mymax[si]));
            float inv = __fdividef(1.f, norm + 1e-6f);
#pragma unroll
            for (int tj = 0; tj < 2; tj++)
                s.chat[(head * 16 + s0 + si) * 16 + t0 + tj] = Cc[si][tj] * inv;
        }
    }
    __syncthreads();

    // ---- ht = Chat @ v (register v, f32x2 packed), LN, gating, store ----
    {
        unsigned long long vp[8];
#pragma unroll
        for (int i = 0; i < 8; i++)
            vp[i] = pack2(s.qkv[(2 * i) * QLD + 512 + tid],
                          s.qkv[(2 * i + 1) * QLD + 512 + tid]);

        int head = tid >> 6;
        const float* chrow = s.chat + head * 256;
        float acc[16];
#pragma unroll
        for (int t = 0; t < 16; t++) {
            unsigned long long a2 = 0ULL;
#pragma unroll
            for (int u4 = 0; u4 < 4; u4++) {
                float4 c = *(const float4*)(chrow + t * 16 + u4 * 4);
                fma2(a2, pack2(c.x, c.y), vp[u4 * 2]);
                fma2(a2, pack2(c.z, c.w), vp[u4 * 2 + 1]);
            }
            float lo, hi;
            unpack2(a2, lo, hi);
            acc[t] = lo + hi;
        }
        // per-warp (32-channel) partial sums for LN over 64-channel heads
#pragma unroll
        for (int t = 0; t < 16; t++) {
            float sv = acc[t];
            float qv = acc[t] * acc[t];
#pragma unroll
            for (int off = 16; off >= 1; off >>= 1) {
                sv += __shfl_xor_sync(0xffffffffu, sv, off);
                qv += __shfl_xor_sync(0xffffffffu, qv, off);
            }
            if (lane == 0) {
                s.red[warp * 16 + t]       = sv;
                s.red[128 + warp * 16 + t] = qv;
            }
        }
        __syncthreads();

        int pw = warp ^ 1;
        float skipv = skip[tid];
        float lnv   = lnw[tid];
#pragma unroll
        for (int t = 0; t < 16; t++) {
            float sv = s.red[warp * 16 + t] + s.red[pw * 16 + t];
            float qv = s.red[128 + warp * 16 + t] + s.red[128 + pw * 16 + t];
            float mu = sv * (1.f / 64.f);
            float var = qv * (1.f / 64.f) - mu * mu;
            float rstd = rsqrtf(var + 1e-5f);
            float hn = (acc[t] - mu) * rstd * lnv;
            size_t m = rowbase + ((size_t)t << 10);
            float z = g_up[m * 512 + 256 + tid];
            g_hs[m * 256 + tid] = (hn + skipv * s.xcs[t * XLD + tid]) * siluf(z);
        }
    }
}

// =====================================================================
// Kernel 3: down projection, out[b,c,t,h,w] = h_state[m,:] @ W_down
//   128x128 tile (full N), 8x8 micro (f32x2 packed), transposed A at 129
// =====================================================================
__global__ __launch_bounds__(256) void k_down(const float* __restrict__ Wd,
                                              float* __restrict__ out)
{
    extern __shared__ float sm[];
    float* As = sm;              // [64 k][129 m-padded]
    float* Bs = sm + 64 * 129;   // [64 k][128 n]

    const int tid = threadIdx.x;
    const int m0 = blockIdx.x * 128;
    const int mx = tid & 15, ny = tid >> 4;

    unsigned long long acc2[4][8];
#pragma unroll
    for (int i = 0; i < 4; i++)
#pragma unroll
        for (int j = 0; j < 8; j++) acc2[i][j] = 0ULL;

    for (int kc = 0; kc < 256; kc += 64) {
        {
            // A: float4 along k, scatter-transpose into As[k][m] (stride 129)
            int kx4 = (tid & 15) * 4, mr = tid >> 4;
#pragma unroll
            for (int p = 0; p < 8; p++) {
                int m = mr + p * 16;
                float4 v = *(const float4*)(g_hs + (size_t)(m0 + m) * 256 + kc + kx4);
                As[(kx4 + 0) * 129 + m] = v.x;
                As[(kx4 + 1) * 129 + m] = v.y;
                As[(kx4 + 2) * 129 + m] = v.z;
                As[(kx4 + 3) * 129 + m] = v.w;
            }
            int n4 = (tid & 31) * 4, kr = tid >> 5;
#pragma unroll
            for (int p = 0; p < 8; p++) {
                int k = kr + p * 8;
                *(float4*)(Bs + k * 128 + n4) = *(const float4*)(Wd + (size_t)(kc + k) * 128 + n4);
            }
        }
        __syncthreads();
#pragma unroll 4
        for (int k = 0; k < 64; k++) {
            float av[8];
#pragma unroll
            for (int i = 0; i < 8; i++) av[i] = As[k * 129 + mx + 16 * i];
            float4 b0 = *(const float4*)(Bs + k * 128 + ny * 4);
            float4 b1 = *(const float4*)(Bs + k * 128 + 64 + ny * 4);
            unsigned long long ap[4];
            ap[0] = pack2(av[0], av[1]); ap[1] = pack2(av[2], av[3]);
            ap[2] = pack2(av[4], av[5]); ap[3] = pack2(av[6], av[7]);
            unsigned long long bb[8];
            bb[0] = pack2(b0.x, b0.x); bb[1] = pack2(b0.y, b0.y);
            bb[2] = pack2(b0.z, b0.z); bb[3] = pack2(b0.w, b0.w);
            bb[4] = pack2(b1.x, b1.x); bb[5] = pack2(b1.y, b1.y);
            bb[6] = pack2(b1.z, b1.z); bb[7] = pack2(b1.w, b1.w);
#pragma unroll
            for (int i = 0; i < 4; i++)
#pragma unroll
                for (int j = 0; j < 8; j++) fma2(acc2[i][j], ap[i], bb[j]);
        }
        __syncthreads();
    }

    float acc[8][8];
#pragma unroll
    for (int i = 0; i < 4; i++)
#pragma unroll
        for (int j = 0; j < 8; j++) unpack2(acc2[i][j], acc[2 * i][j], acc[2 * i + 1][j]);

    const int hw0 = m0 & 1023;
    const int bt = m0 >> 10;
    float* ob = out + (size_t)(bt >> 4) * 2097152 + (size_t)(bt & 15) * 1024 + hw0;
#pragma unroll
    for (int j = 0; j < 8; j++) {
        int c = ny * 4 + (j & 3) + ((j >> 2) << 6);
#pragma unroll
        for (int i = 0; i < 8; i++)
            ob[(size_t)c * 16384 + mx + 16 * i] = acc[i][j];
    }
}

// =====================================================================
// launch
// =====================================================================
extern "C" void kernel_launch(void* const* d_in, const int* in_sizes, int n_in,
                              void* d_out, int out_size)
{
    const float* x    = (const float*)d_in[0];
    const float* Wup  = (const float*)d_in[1];
    const float* cw   = (const float*)d_in[2];
    const float* cb   = (const float*)d_in[3];
    const float* Wq   = (const float*)d_in[4];
    const float* Wk   = (const float*)d_in[5];
    const float* Wv   = (const float*)d_in[6];
    const float* igw  = (const float*)d_in[7];
    const float* igb  = (const float*)d_in[8];
    const float* fgw  = (const float*)d_in[9];
    const float* fgb  = (const float*)d_in[10];
    const float* lnw  = (const float*)d_in[11];
    const float* skip = (const float*)d_in[12];
    const float* Wd   = (const float*)d_in[13];
    float* out = (float*)d_out;

    (void)in_sizes; (void)n_in; (void)out_size;

    const int smem_up   = (64 * 128 + 64 * 128) * (int)sizeof(float);  // 64 KB
    const int smem_mid  = (int)sizeof(SM2);                            // ~70.3 KB
    const int smem_down = (64 * 129 + 64 * 128) * (int)sizeof(float);  // ~64.3 KB

    cudaFuncSetAttribute(k_up,   cudaFuncAttributeMaxDynamicSharedMemorySize, smem_up);
    cudaFuncSetAttribute(k_mid,  cudaFuncAttributeMaxDynamicSharedMemorySize, smem_mid);
    cudaFuncSetAttribute(k_down, cudaFuncAttributeMaxDynamicSharedMemorySize, smem_down);

    k_up<<<dim3(4, 1024), 256, smem_up>>>(x, Wup);
    k_mid<<<8192, 256, smem_mid>>>(cw, cb, Wq, Wk, Wv, igw, igb, fgw, fgb, lnw, skip);
    k_down<<<1024, 256, smem_down>>>(Wd, out);
}

// round 15
// speedup vs baseline: 1.5209x; 1.5209x over previous
#include <cuda_runtime.h>
#include <math.h>

// ---------------- problem constants ----------------
#define MTOT  131072          // B*T*H*W rows, m = ((b*T+t)*H+h)*W+w
#define QLD   772             // qkv smem row stride (floats): mult of 4, !=0 mod 32
#define XLD   260             // xc smem row stride

// ---------------- scratch (device globals; no allocs) ----------------
__device__ float g_up[(size_t)MTOT * 512];   // up-projection output [M,512] (x_m | z)
__device__ float g_hs[(size_t)MTOT * 256];   // h_state [M,256]

__device__ __forceinline__ float siluf(float x) { return x / (1.f + __expf(-x)); }

// ---------------- packed f32x2 helpers (B300 double-rate fp32) ----------------
__device__ __forceinline__ unsigned long long pack2(float lo, float hi) {
    unsigned long long r;
    asm("mov.b64 %0, {%1, %2};" : "=l"(r) : "f"(lo), "f"(hi));
    return r;
}
__device__ __forceinline__ void fma2(unsigned long long& d,
                                     unsigned long long a, unsigned long long b) {
    asm("fma.rn.f32x2 %0, %1, %2, %0;" : "+l"(d) : "l"(a), "l"(b));
}
__device__ __forceinline__ void unpack2(unsigned long long v, float& lo, float& hi) {
    asm("mov.b64 {%0, %1}, %2;" : "=f"(lo), "=f"(hi) : "l"(v));
}

// =====================================================================
// Kernel 1: up projection GEMM  up[m,n] = sum_k xs[m,k] * W_up[k,n]
//   128x128 tile, 8x8 micro (f32x2 packed), kc=64
// =====================================================================
__global__ __launch_bounds__(256) void k_up(const float* __restrict__ x,
                                            const float* __restrict__ Wup)
{
    extern __shared__ float sm[];
    float* As = sm;             // [64 k][128 m]
    float* Bs = sm + 64 * 128;  // [64 k][128 n]

    const int tid = threadIdx.x;
    const int n0 = blockIdx.x * 128;
    const int m0 = blockIdx.y * 128;
    const int hw0 = m0 & 1023;
    const int bt  = m0 >> 10;           // b*16 + t
    const float* xb = x + (size_t)(bt >> 4) * 2097152 + (size_t)(bt & 15) * 1024 + hw0;

    const int mx = tid & 15, ny = tid >> 4;
    const int l4 = (tid & 31) * 4, kr = tid >> 5;  // loader coords

    unsigned long long acc2[4][8];      // [m-pair][n]
#pragma unroll
    for (int i = 0; i < 4; i++)
#pragma unroll
        for (int j = 0; j < 8; j++) acc2[i][j] = 0ULL;

    for (int kc = 0; kc < 128; kc += 64) {
#pragma unroll
        for (int p = 0; p < 8; p++) {
            int k = kr + p * 8;
            *(float4*)(As + k * 128 + l4) = *(const float4*)(xb + (size_t)(kc + k) * 16384 + l4);
            *(float4*)(Bs + k * 128 + l4) = *(const float4*)(Wup + (size_t)(kc + k) * 512 + n0 + l4);
        }
        __syncthreads();
#pragma unroll 4
        for (int k = 0; k < 64; k++) {
            float4 a0 = *(const float4*)(As + k * 128 + mx * 4);
            float4 a1 = *(const float4*)(As + k * 128 + 64 + mx * 4);
            float4 b0 = *(const float4*)(Bs + k * 128 + ny * 4);
            float4 b1 = *(const float4*)(Bs + k * 128 + 64 + ny * 4);
            unsigned long long ap[4];
            ap[0] = pack2(a0.x, a0.y); ap[1] = pack2(a0.z, a0.w);
            ap[2] = pack2(a1.x, a1.y); ap[3] = pack2(a1.z, a1.w);
            unsigned long long bb[8];
            bb[0] = pack2(b0.x, b0.x); bb[1] = pack2(b0.y, b0.y);
            bb[2] = pack2(b0.z, b0.z); bb[3] = pack2(b0.w, b0.w);
            bb[4] = pack2(b1.x, b1.x); bb[5] = pack2(b1.y, b1.y);
            bb[6] = pack2(b1.z, b1.z); bb[7] = pack2(b1.w, b1.w);
#pragma unroll
            for (int i = 0; i < 4; i++)
#pragma unroll
                for (int j = 0; j < 8; j++) fma2(acc2[i][j], ap[i], bb[j]);
        }
        __syncthreads();
    }

    float acc[8][8];
#pragma unroll
    for (int i = 0; i < 4; i++)
#pragma unroll
        for (int j = 0; j < 8; j++) unpack2(acc2[i][j], acc[2 * i][j], acc[2 * i + 1][j]);

#pragma unroll
    for (int i = 0; i < 8; i++) {
        int m = m0 + mx * 4 + (i & 3) + ((i >> 2) << 6);
        float* ob = g_up + (size_t)m * 512 + n0;
        *(float4*)(ob + ny * 4)      = make_float4(acc[i][0], acc[i][1], acc[i][2], acc[i][3]);
        *(float4*)(ob + 64 + ny * 4) = make_float4(acc[i][4], acc[i][5], acc[i][6], acc[i][7]);
    }
}

// =====================================================================
// Kernel 2: fused conv/qkv/gates/mLSTM/LN/gating, one CTA per sequence
//   xc in smem; q/k/v via 16B broadcast loads (no shuffles, low regs)
// =====================================================================
struct SM2 {
    float qkv[16 * QLD];        // per t: q[0,256) k[256,512) v[512,768)
    float xcs[16 * XLD];        // conv+silu output rows
    float chat[4 * 16 * 16];
    float lf[4 * 17];
    float igv[64];
    float fgv[64];
    float red[2 * 8 * 16];      // [sum|sq][warp][t]
};

__global__ __launch_bounds__(256, 3) void k_mid(
    const float* __restrict__ cw,  const float* __restrict__ cb,
    const float* __restrict__ Wq,  const float* __restrict__ Wk,
    const float* __restrict__ Wv,
    const float* __restrict__ igw, const float* __restrict__ igb,
    const float* __restrict__ fgw, const float* __restrict__ fgb,
    const float* __restrict__ lnw, const float* __restrict__ skip)
{
    extern __shared__ char smraw[];
    SM2& s = *reinterpret_cast<SM2*>(smraw);
    const int tid  = threadIdx.x;
    const int lane = tid & 31;
    const int warp = tid >> 5;
    const int bl4  = tid & ~3;          // 4-channel block base
    const int e    = tid & 3;
    const int seq = blockIdx.x;
    const int b = seq >> 10, hw = seq & 1023;
    const size_t rowbase = ((size_t)(b * 16) << 10) + hw;   // + (t<<10) per step

    // ---- loop1: xm block via LDG.128 broadcast; conv window in 3 regs;
    //      xc -> smem; v = blockdiag(Wv)@xm -> qkv ----
    {
        float c0 = cw[tid], c1 = cw[256 + tid], c2 = cw[512 + tid], c3 = cw[768 + tid];
        float cbv = cb[tid];
        float4 wv = *(const float4*)(Wv + 4 * tid);
        float w0 = 0.f, w1 = 0.f, w2 = 0.f;   // xm[t-3], xm[t-2], xm[t-1] (own channel)
#pragma unroll
        for (int t = 0; t < 16; t++) {
            float4 xmb = *(const float4*)(g_up + (rowbase + ((size_t)t << 10)) * 512 + bl4);
            float xmt = (e == 0) ? xmb.x : (e == 1) ? xmb.y : (e == 2) ? xmb.z : xmb.w;
            float a = cbv + c3 * xmt;
            if (t >= 1) a += c2 * w2;
            if (t >= 2) a += c1 * w1;
            if (t >= 3) a += c0 * w0;
            s.xcs[t * XLD + tid] = siluf(a);
            s.qkv[t * QLD + 512 + tid] =
                wv.x * xmb.x + wv.y * xmb.y + wv.z * xmb.z + wv.w * xmb.w;
            w0 = w1; w1 = w2; w2 = xmt;
        }
    }
    __syncwarp();   // xc producers/consumers are within the same warp (4-lane blocks)

    // ---- loop2: q/k from xc block via LDS.128 broadcast ----
    {
        float4 wq = *(const float4*)(Wq + 4 * tid);
        float4 wk = *(const float4*)(Wk + 4 * tid);
#pragma unroll
        for (int t = 0; t < 16; t++) {
            float4 xcb = *(const float4*)(&s.xcs[t * XLD + bl4]);
            s.qkv[t * QLD + tid] =
                wq.x * xcb.x + wq.y * xcb.y + wq.z * xcb.z + wq.w * xcb.w;
            s.qkv[t * QLD + 256 + tid] =
                wk.x * xcb.x + wk.y * xcb.y + wk.z * xcb.z + wk.w * xcb.w;
        }
    }
    __syncthreads();

    // ---- gates: ig/fg [t,h] over 768 inputs; 16 lanes split-K + shfl reduce ----
    {
        int t = tid >> 4, p = tid & 15;
        const float* row = s.qkv + t * QLD;
        float ai[4] = {0.f, 0.f, 0.f, 0.f}, af[4] = {0.f, 0.f, 0.f, 0.f};
#pragma unroll
        for (int ii = 0; ii < 12; ii++) {
            int idx = p * 4 + ii * 64;
            float4 xv = *(const float4*)(row + idx);
            float vals[4] = {xv.x, xv.y, xv.z, xv.w};
#pragma unroll
            for (int ee = 0; ee < 4; ee++) {
                float val = vals[ee];
                float4 wi = *(const float4*)(igw + (idx + ee) * 4);
                float4 wf = *(const float4*)(fgw + (idx + ee) * 4);
                ai[0] += val * wi.x; ai[1] += val * wi.y; ai[2] += val * wi.z; ai[3] += val * wi.w;
                af[0] += val * wf.x; af[1] += val * wf.y; af[2] += val * wf.z; af[3] += val * wf.w;
            }
        }
#pragma unroll
        for (int off = 1; off < 16; off <<= 1) {
#pragma unroll
            for (int h = 0; h < 4; h++) {
                ai[h] += __shfl_xor_sync(0xffffffffu, ai[h], off);
                af[h] += __shfl_xor_sync(0xffffffffu, af[h], off);
            }
        }
        if (p == 0) {
#pragma unroll
            for (int h = 0; h < 4; h++) {
                s.igv[t * 4 + h] = ai[h] + igb[h];
                s.fgv[t * 4 + h] = af[h] + fgb[h];
            }
        }
    }
    __syncthreads();

    // ---- log-sigmoid of forget gates: parallel over 64 (t,h), then prefix ----
    if (tid < 64) {
        int t = tid >> 2, h = tid & 3;
        float xg = s.fgv[t * 4 + h];
        s.lf[h * 17 + t + 1] = fminf(xg, 0.f) - __logf(1.f + __expf(-fabsf(xg)));
    }
    __syncthreads();
    if (tid < 4) {
        int h = tid;
        float run = 0.f;
        s.lf[h * 17 + 0] = 0.f;
#pragma unroll
        for (int t = 0; t < 16; t++) {
            run += s.lf[h * 17 + t + 1];
            s.lf[h * 17 + t + 1] = run;
        }
    }
    __syncthreads();

    // ---- qk + gate matrix + normalizer -> chat (per head: 64 thr, 2x2 tiles) ----
    {
        int head = tid >> 6, w = tid & 63;
        int s0 = (w >> 3) * 2;
        int t0 = (w & 7) * 2;
        const float* q0 = s.qkv + s0 * QLD + head * 64;
        const float* q1 = q0 + QLD;
        const float* k0 = s.qkv + t0 * QLD + 256 + head * 64;
        const float* k1 = k0 + QLD;
        float qk00 = 0.f, qk01 = 0.f, qk10 = 0.f, qk11 = 0.f;
#pragma unroll 4
        for (int d4 = 0; d4 < 16; d4++) {
            float4 a0 = *(const float4*)(q0 + d4 * 4);
            float4 a1 = *(const float4*)(q1 + d4 * 4);
            float4 b0 = *(const float4*)(k0 + d4 * 4);
            float4 b1 = *(const float4*)(k1 + d4 * 4);
            qk00 += a0.x * b0.x + a0.y * b0.y + a0.z * b0.z + a0.w * b0.w;
            qk01 += a0.x * b1.x + a0.y * b1.y + a0.z * b1.z + a0.w * b1.w;
            qk10 += a1.x * b0.x + a1.y * b0.y + a1.z * b0.z + a1.w * b0.w;
            qk11 += a1.x * b1.x + a1.y * b1.y + a1.z * b1.z + a1.w * b1.w;
        }
        float qk[2][2] = {{qk00, qk01}, {qk10, qk11}};
        float logD[2][2], mymax[2];
#pragma unroll
        for (int si = 0; si < 2; si++) {
            int ss = s0 + si;
            mymax[si] = -INFINITY;
#pragma unroll
            for (int tj = 0; tj < 2; tj++) {
                int t_ = t0 + tj;
                float v = (t_ <= ss)
                    ? (s.lf[head * 17 + ss + 1] - s.lf[head * 17 + t_ + 1] + s.igv[t_ * 4 + head])
                    : -INFINITY;
                logD[si][tj] = v;
                mymax[si] = fmaxf(mymax[si], v);
            }
        }
#pragma unroll
        for (int off = 1; off < 8; off <<= 1) {
            mymax[0] = fmaxf(mymax[0], __shfl_xor_sync(0xffffffffu, mymax[0], off));
            mymax[1] = fmaxf(mymax[1], __shfl_xor_sync(0xffffffffu, mymax[1], off));
        }
        float Cc[2][2], rowsum[2] = {0.f, 0.f};
#pragma unroll
        for (int si = 0; si < 2; si++)
#pragma unroll
            for (int tj = 0; tj < 2; tj++) {
                float Dv = __expf(logD[si][tj] - mymax[si]);   // __expf(-inf)=0 masked
                float Cv = qk[si][tj] * 0.125f * Dv;
                Cc[si][tj] = Cv;
                rowsum[si] += Cv;
            }
#pragma unroll
        for (int off = 1; off < 8; off <<= 1) {
            rowsum[0] += __shfl_xor_sync(0xffffffffu, rowsum[0], off);
            rowsum[1] += __shfl_xor_sync(0xffffffffu, rowsum[1], off);
        }
#pragma unroll
        for (int si = 0; si < 2; si++) {
            float norm = fmaxf(fabsf(rowsum[si]), __expf(-mymax[si]));
            float inv = __fdividef(1.f, norm + 1e-6f);
#pragma unroll
            for (int tj = 0; tj < 2; tj++)
                s.chat[(head * 16 + s0 + si) * 16 + t0 + tj] = Cc[si][tj] * inv;
        }
    }
    __syncthreads();

    // ---- ht = Chat @ v (register v, f32x2 packed), LN, gating, store ----
    {
        unsigned long long vp[8];
#pragma unroll
        for (int i = 0; i < 8; i++)
            vp[i] = pack2(s.qkv[(2 * i) * QLD + 512 + tid],
                          s.qkv[(2 * i + 1) * QLD + 512 + tid]);

        int head = tid >> 6;
        const float* chrow = s.chat + head * 256;
        float acc[16];
#pragma unroll
        for (int t = 0; t < 16; t++) {
            unsigned long long a2 = 0ULL;
#pragma unroll
            for (int u4 = 0; u4 < 4; u4++) {
                float4 c = *(const float4*)(chrow + t * 16 + u4 * 4);
                fma2(a2, pack2(c.x, c.y), vp[u4 * 2]);
                fma2(a2, pack2(c.z, c.w), vp[u4 * 2 + 1]);
            }
            float lo, hi;
            unpack2(a2, lo, hi);
            acc[t] = lo + hi;
        }
        // per-warp (32-channel) partial sums for LN over 64-channel heads
#pragma unroll
        for (int t = 0; t < 16; t++) {
            float sv = acc[t];
            float qv = acc[t] * acc[t];
#pragma unroll
            for (int off = 16; off >= 1; off >>= 1) {
                sv += __shfl_xor_sync(0xffffffffu, sv, off);
                qv += __shfl_xor_sync(0xffffffffu, qv, off);
            }
            if (lane == 0) {
                s.red[warp * 16 + t]       = sv;
                s.red[128 + warp * 16 + t] = qv;
            }
        }
        __syncthreads();

        int pw = warp ^ 1;
        float skipv = skip[tid];
        float lnv   = lnw[tid];
#pragma unroll
        for (int t = 0; t < 16; t++) {
            float sv = s.red[warp * 16 + t] + s.red[pw * 16 + t];
            float qv = s.red[128 + warp * 16 + t] + s.red[128 + pw * 16 + t];
            float mu = sv * (1.f / 64.f);
            float var = qv * (1.f / 64.f) - mu * mu;
            float rstd = rsqrtf(var + 1e-5f);
            float hn = (acc[t] - mu) * rstd * lnv;
            size_t m = rowbase + ((size_t)t << 10);
            float z = g_up[m * 512 + 256 + tid];
            g_hs[m * 256 + tid] = (hn + skipv * s.xcs[t * XLD + tid]) * siluf(z);
        }
    }
}

// =====================================================================
// Kernel 3: down projection, out[b,c,t,h,w] = h_state[m,:] @ W_down
//   128x128 tile (full N), 8x8 micro (f32x2 packed), transposed A at 129
// =====================================================================
__global__ __launch_bounds__(256) void k_down(const float* __restrict__ Wd,
                                              float* __restrict__ out)
{
    extern __shared__ float sm[];
    float* As = sm;              // [64 k][129 m-padded]
    float* Bs = sm + 64 * 129;   // [64 k][128 n]

    const int tid = threadIdx.x;
    const int m0 = blockIdx.x * 128;
    const int mx = tid & 15, ny = tid >> 4;

    unsigned long long acc2[4][8];
#pragma unroll
    for (int i = 0; i < 4; i++)
#pragma unroll
        for (int j = 0; j < 8; j++) acc2[i][j] = 0ULL;

    for (int kc = 0; kc < 256; kc += 64) {
        {
            // A: float4 along k, scatter-transpose into As[k][m] (stride 129)
            int kx4 = (tid & 15) * 4, mr = tid >> 4;
#pragma unroll
            for (int p = 0; p < 8; p++) {
                int m = mr + p * 16;
                float4 v = *(const float4*)(g_hs + (size_t)(m0 + m) * 256 + kc + kx4);
                As[(kx4 + 0) * 129 + m] = v.x;
                As[(kx4 + 1) * 129 + m] = v.y;
                As[(kx4 + 2) * 129 + m] = v.z;
                As[(kx4 + 3) * 129 + m] = v.w;
            }
            int n4 = (tid & 31) * 4, kr = tid >> 5;
#pragma unroll
            for (int p = 0; p < 8; p++) {
                int k = kr + p * 8;
                *(float4*)(Bs + k * 128 + n4) = *(const float4*)(Wd + (size_t)(kc + k) * 128 + n4);
            }
        }
        __syncthreads();
#pragma unroll 4
        for (int k = 0; k < 64; k++) {
            float av[8];
#pragma unroll
            for (int i = 0; i < 8; i++) av[i] = As[k * 129 + mx + 16 * i];
            float4 b0 = *(const float4*)(Bs + k * 128 + ny * 4);
            float4 b1 = *(const float4*)(Bs + k * 128 + 64 + ny * 4);
            unsigned long long ap[4];
            ap[0] = pack2(av[0], av[1]); ap[1] = pack2(av[2], av[3]);
            ap[2] = pack2(av[4], av[5]); ap[3] = pack2(av[6], av[7]);
            unsigned long long bb[8];
            bb[0] = pack2(b0.x, b0.x); bb[1] = pack2(b0.y, b0.y);
            bb[2] = pack2(b0.z, b0.z); bb[3] = pack2(b0.w, b0.w);
            bb[4] = pack2(b1.x, b1.x); bb[5] = pack2(b1.y, b1.y);
            bb[6] = pack2(b1.z, b1.z); bb[7] = pack2(b1.w, b1.w);
#pragma unroll
            for (int i = 0; i < 4; i++)
#pragma unroll
                for (int j = 0; j < 8; j++) fma2(acc2[i][j], ap[i], bb[j]);
        }
        __syncthreads();
    }

    float acc[8][8];
#pragma unroll
    for (int i = 0; i < 4; i++)
#pragma unroll
        for (int j = 0; j < 8; j++) unpack2(acc2[i][j], acc[2 * i][j], acc[2 * i + 1][j]);

    const int hw0 = m0 & 1023;
    const int bt = m0 >> 10;
    float* ob = out + (size_t)(bt >> 4) * 2097152 + (size_t)(bt & 15) * 1024 + hw0;
#pragma unroll
    for (int j = 0; j < 8; j++) {
        int c = ny * 4 + (j & 3) + ((j >> 2) << 6);
#pragma unroll
        for (int i = 0; i < 8; i++)
            ob[(size_t)c * 16384 + mx + 16 * i] = acc[i][j];
    }
}

// =====================================================================
// launch
// =====================================================================
extern "C" void kernel_launch(void* const* d_in, const int* in_sizes, int n_in,
                              void* d_out, int out_size)
{
    const float* x    = (const float*)d_in[0];
    const float* Wup  = (const float*)d_in[1];
    const float* cw   = (const float*)d_in[2];
    const float* cb   = (const float*)d_in[3];
    const float* Wq   = (const float*)d_in[4];
    const float* Wk   = (const float*)d_in[5];
    const float* Wv   = (const float*)d_in[6];
    const float* igw  = (const float*)d_in[7];
    const float* igb  = (const float*)d_in[8];
    const float* fgw  = (const float*)d_in[9];
    const float* fgb  = (const float*)d_in[10];
    const float* lnw  = (const float*)d_in[11];
    const float* skip = (const float*)d_in[12];
    const float* Wd   = (const float*)d_in[13];
    float* out = (float*)d_out;

    (void)in_sizes; (void)n_in; (void)out_size;

    const int smem_up   = (64 * 128 + 64 * 128) * (int)sizeof(float);  // 64 KB
    const int smem_mid  = (int)sizeof(SM2);                            // ~70.3 KB
    const int smem_down = (64 * 129 + 64 * 128) * (int)sizeof(float);  // ~64.3 KB

    cudaFuncSetAttribute(k_up,   cudaFuncAttributeMaxDynamicSharedMemorySize, smem_up);
    cudaFuncSetAttribute(k_mid,  cudaFuncAttributeMaxDynamicSharedMemorySize, smem_mid);
    cudaFuncSetAttribute(k_down, cudaFuncAttributeMaxDynamicSharedMemorySize, smem_down);

    k_up<<<dim3(4, 1024), 256, smem_up>>>(x, Wup);
    k_mid<<<8192, 256, smem_mid>>>(cw, cb, Wq, Wk, Wv, igw, igb, fgw, fgb, lnw, skip);
    k_down<<<1024, 256, smem_down>>>(Wd, out);
}